// round 1
// baseline (speedup 1.0000x reference)
#include <cuda_runtime.h>
#include <math.h>

#define BB 8
#define CC 32
#define HH 120
#define WW 160
#define HW (HH*WW)
#define CHW (CC*HW)
#define OUT_ROW (12 + CHW)
#define NBLK (HW/256)   /* 75 */
#define OCC_THRES 0.1f

// ---------------- static device state (no dynamic allocation) ----------------
__device__ float g_jfx[BB*CHW];
__device__ float g_jfy[BB*CHW];
__device__ float g_R[BB][9];
__device__ float g_t[BB][3];
__device__ float g_part[BB][NBLK][27];

// ---------------- init: copy R,t inputs into iteration state ----------------
__global__ void init_state_kernel(const float* __restrict__ Rin,
                                  const float* __restrict__ tin) {
    int i = threadIdx.x;
    if (i < 72) g_R[i/9][i%9] = Rin[i];
    if (i < 24) g_t[i/3][i%3] = tin[i];
}

// ---------------- Sobel gradient (edge-clamped cross-correlation) ------------
__global__ void sobel_kernel(const float* __restrict__ F1) {
    int i = blockIdx.x*blockDim.x + threadIdx.x;
    if (i >= BB*CHW) return;
    int x  = i % WW;
    int y  = (i / WW) % HH;
    int bc = i / HW;
    const float* F = F1 + (size_t)bc*HW;
    int xm = max(x-1,0), xp = min(x+1,WW-1);
    int ym = max(y-1,0), yp = min(y+1,HH-1);
    float f_mm = F[ym*WW+xm], f_m0 = F[ym*WW+x], f_mp = F[ym*WW+xp];
    float f_0m = F[y *WW+xm],                    f_0p = F[y *WW+xp];
    float f_pm = F[yp*WW+xm], f_p0 = F[yp*WW+x], f_pp = F[yp*WW+xp];
    float dx = (f_mp - f_mm) + 2.0f*(f_0p - f_0m) + (f_pp - f_pm);
    float dy = (f_pm - f_mm) + 2.0f*(f_p0 - f_m0) + (f_pp - f_mp);
    float mag = sqrtf(dx*dx + dy*dy + 1e-8f);
    g_jfx[i] = dx / mag;
    g_jfy[i] = dy / mag;
}

// ---------------- per-pixel accumulation kernel ------------------------------
__global__ void __launch_bounds__(256)
accum_kernel(const float* __restrict__ F0, const float* __restrict__ F1,
             const float* __restrict__ invD0, const float* __restrict__ invD1,
             const float* __restrict__ Kmat, float* __restrict__ out, int last)
{
    const int b   = blockIdx.y;
    const int pix = blockIdx.x*blockDim.x + threadIdx.x;   // 0..19199 exactly
    const int x   = pix % WW;
    const int y   = pix / WW;

    // pose + intrinsics (broadcast loads)
    const float R0=g_R[b][0], R1=g_R[b][1], R2=g_R[b][2];
    const float R3=g_R[b][3], R4=g_R[b][4], R5=g_R[b][5];
    const float R6=g_R[b][6], R7=g_R[b][7], R8=g_R[b][8];
    const float t0=g_t[b][0], t1=g_t[b][1], t2=g_t[b][2];
    const float fx=Kmat[b*4+0], fy=Kmat[b*4+1], cx=Kmat[b*4+2], cy=Kmat[b*4+3];

    const float px = ((float)x - cx) / fx;
    const float py = ((float)y - cy) / fy;
    const float id0 = invD0[(size_t)b*HW + pix];

    // warp inverse depth: warped = R*[px,py,1] + t*invD0
    const float X = R0*px + R1*py + R2 + t0*id0;
    const float Y = R3*px + R4*py + R5 + t1*id0;
    const float S = R6*px + R7*py + R8 + t2*id0;
    const float u = (X/S)*fx + cx;
    const float v = (Y/S)*fy + cy;
    const float inv_z = id0 / S;

    const bool inview = (u > 0.0f) && (u < (float)(WW-1)) &&
                        (v > 0.0f) && (v < (float)(HH-1));

    // clipped bilinear setup
    const float uc = fminf(fmaxf(u, 0.0f), (float)(WW-1));
    const float vc = fminf(fmaxf(v, 0.0f), (float)(HH-1));
    const float x0f = floorf(uc), y0f = floorf(vc);
    const float wx = uc - x0f,  wy = vc - y0f;
    const int x0 = (int)x0f, y0 = (int)y0f;
    const int x1 = min(x0+1, WW-1), y1 = min(y0+1, HH-1);
    const int i00 = y0*WW+x0, i01 = y0*WW+x1, i10 = y1*WW+x0, i11 = y1*WW+x1;
    const float w00 = (1.0f-wx)*(1.0f-wy), w01 = wx*(1.0f-wy);
    const float w10 = (1.0f-wx)*wy,        w11 = wx*wy;

    // occlusion (invD1 warp, single channel)
    const float* D1 = invD1 + (size_t)b*HW;
    const float invD1w = D1[i00]*w00 + D1[i01]*w01 + D1[i10]*w10 + D1[i11]*w11;
    const bool occ = !((inv_z > invD1w - OCC_THRES) && inview);

    // jacobian warp: warped = R*[px,py,invD0] + t
    const float xj = R0*px + R1*py + R2*id0 + t0;
    const float yj = R3*px + R4*py + R5*id0 + t1;
    const float iz = R6*px + R7*py + R8*id0 + t2;
    const float Jx[6] = { fx*(-xj*yj), fx*(1.0f+xj*xj), fx*(-yj),
                          fx*iz,       0.0f,            fx*(-iz*xj) };
    const float Jy[6] = { fy*(-1.0f-yj*yj), fy*(xj*yj), fy*xj,
                          0.0f,             fy*iz,      fy*(-iz*yj) };

    // channel loop -> 5 scalar sums
    float saa = 0.f, sab = 0.f, sbb = 0.f, sar = 0.f, sbr = 0.f;
    const float* F1b  = F1    + (size_t)b*CHW;
    const float* F0b  = F0    + (size_t)b*CHW;
    const float* JXb  = g_jfx + (size_t)b*CHW;
    const float* JYb  = g_jfy + (size_t)b*CHW;

    #pragma unroll 4
    for (int c = 0; c < CC; ++c) {
        const int o = c*HW;
        const float f1w = F1b[o+i00]*w00 + F1b[o+i01]*w01 +
                          F1b[o+i10]*w10 + F1b[o+i11]*w11;
        const float ax  = JXb[o+i00]*w00 + JXb[o+i01]*w01 +
                          JXb[o+i10]*w10 + JXb[o+i11]*w11;
        const float ay  = JYb[o+i00]*w00 + JYb[o+i01]*w01 +
                          JYb[o+i10]*w10 + JYb[o+i11]*w11;
        const float r   = occ ? 0.001f : (f1w - F0b[o + pix]);
        const float wgt = __fdividef(1.0f, 1.0f + r*r);
        const float wr  = wgt * r;
        saa += ax*ax;  sab += ax*ay;  sbb += ay*ay;
        sar += ax*wr;  sbr += ay*wr;
        if (last) out[(size_t)b*OUT_ROW + 12 + o + pix] = wgt;
    }

    // per-pixel contribution: 21 (upper-tri 6x6) + 6 (rhs)
    float acc[27];
    int idx = 0;
    #pragma unroll
    for (int k = 0; k < 6; ++k)
        #pragma unroll
        for (int l = k; l < 6; ++l)
            acc[idx++] = saa*Jx[k]*Jx[l] + sab*(Jx[k]*Jy[l] + Jy[k]*Jx[l])
                       + sbb*Jy[k]*Jy[l];
    #pragma unroll
    for (int k = 0; k < 6; ++k)
        acc[idx++] = -(sar*Jx[k] + sbr*Jy[k]);

    // deterministic block reduction: warp shuffle -> smem -> single partial
    #pragma unroll
    for (int j = 0; j < 27; ++j) {
        float s = acc[j];
        #pragma unroll
        for (int off = 16; off > 0; off >>= 1)
            s += __shfl_down_sync(0xffffffffu, s, off);
        acc[j] = s;
    }
    __shared__ float sm[8][27];
    const int warp = threadIdx.x >> 5, lane = threadIdx.x & 31;
    if (lane == 0) {
        #pragma unroll
        for (int j = 0; j < 27; ++j) sm[warp][j] = acc[j];
    }
    __syncthreads();
    if (threadIdx.x < 27) {
        float s = 0.f;
        #pragma unroll
        for (int wp = 0; wp < 8; ++wp) s += sm[wp][threadIdx.x];
        g_part[b][blockIdx.x][threadIdx.x] = s;
    }
}

// ---------------- 6x6 solve + se3 exp + pose update --------------------------
__global__ void solve_kernel(float* __restrict__ out, int last) {
    const int b = blockIdx.x;
    __shared__ double acc[27];
    if (threadIdx.x < 27) {
        double s = 0.0;
        for (int blk = 0; blk < NBLK; ++blk)
            s += (double)g_part[b][blk][threadIdx.x];
        acc[threadIdx.x] = s;
    }
    __syncthreads();
    if (threadIdx.x != 0) return;

    // assemble A (symmetric + damping) and rhs
    double M[6][7];
    {
        double A[6][6];
        int idx = 0;
        for (int k = 0; k < 6; ++k)
            for (int l = k; l < 6; ++l) { A[k][l] = acc[idx]; A[l][k] = acc[idx]; ++idx; }
        for (int k = 0; k < 6; ++k) A[k][k] += 1e-4;
        for (int i = 0; i < 6; ++i) {
            for (int j = 0; j < 6; ++j) M[i][j] = A[i][j];
            M[i][6] = acc[21+i];
        }
    }
    // gaussian elimination with partial pivoting
    for (int col = 0; col < 6; ++col) {
        int p = col;
        double best = fabs(M[col][col]);
        for (int r = col+1; r < 6; ++r) {
            double a = fabs(M[r][col]);
            if (a > best) { best = a; p = r; }
        }
        if (p != col)
            for (int j = 0; j < 7; ++j) { double tmp = M[col][j]; M[col][j] = M[p][j]; M[p][j] = tmp; }
        const double piv = M[col][col];
        for (int r = col+1; r < 6; ++r) {
            const double f = M[r][col] / piv;
            for (int j = col; j < 7; ++j) M[r][j] -= f * M[col][j];
        }
    }
    double dp[6];
    for (int i = 5; i >= 0; --i) {
        double s = M[i][6];
        for (int j = i+1; j < 6; ++j) s -= M[i][j] * dp[j];
        dp[i] = s / M[i][i];
    }

    // se3 exponential
    const double w0 = dp[0], w1 = dp[1], w2 = dp[2];
    const double v0 = dp[3], v1 = dp[4], v2 = dp[5];
    const double th2 = w0*w0 + w1*w1 + w2*w2;
    const double th  = sqrt(th2 + 1e-12);
    const double a   = sin(th) / th;
    const double bbv = (1.0 - cos(th)) / (th2 + 1e-12);
    const double ccv = (1.0 - a) / (th2 + 1e-12);
    const double Wm[3][3] = { {0.0, -w2,  w1},
                              {w2,  0.0, -w0},
                              {-w1, w0,  0.0} };
    double W2[3][3];
    for (int i = 0; i < 3; ++i)
        for (int j = 0; j < 3; ++j) {
            double s = 0.0;
            for (int k = 0; k < 3; ++k) s += Wm[i][k] * Wm[k][j];
            W2[i][j] = s;
        }
    double dR[3][3], Vm[3][3];
    for (int i = 0; i < 3; ++i)
        for (int j = 0; j < 3; ++j) {
            const double I = (i == j) ? 1.0 : 0.0;
            dR[i][j] = I + a  * Wm[i][j] + bbv * W2[i][j];
            Vm[i][j] = I + bbv* Wm[i][j] + ccv * W2[i][j];
        }
    const double dt0 = Vm[0][0]*v0 + Vm[0][1]*v1 + Vm[0][2]*v2;
    const double dt1 = Vm[1][0]*v0 + Vm[1][1]*v1 + Vm[1][2]*v2;
    const double dt2 = Vm[2][0]*v0 + Vm[2][1]*v1 + Vm[2][2]*v2;

    // pose update: t = dR*t + dt ; R = dR*R
    double Rold[9], told[3];
    for (int i = 0; i < 9; ++i) Rold[i] = (double)g_R[b][i];
    for (int i = 0; i < 3; ++i) told[i] = (double)g_t[b][i];

    double tnew[3], Rnew[9];
    for (int i = 0; i < 3; ++i) {
        tnew[i] = dR[i][0]*told[0] + dR[i][1]*told[1] + dR[i][2]*told[2]
                + ((i==0)?dt0:(i==1)?dt1:dt2);
        for (int j = 0; j < 3; ++j)
            Rnew[i*3+j] = dR[i][0]*Rold[0*3+j] + dR[i][1]*Rold[1*3+j] + dR[i][2]*Rold[2*3+j];
    }
    for (int i = 0; i < 9; ++i) g_R[b][i] = (float)Rnew[i];
    for (int i = 0; i < 3; ++i) g_t[b][i] = (float)tnew[i];

    if (last) {
        for (int i = 0; i < 9; ++i) out[(size_t)b*OUT_ROW + i]     = (float)Rnew[i];
        for (int i = 0; i < 3; ++i) out[(size_t)b*OUT_ROW + 9 + i] = (float)tnew[i];
    }
}

// ---------------- launch ------------------------------------------------------
extern "C" void kernel_launch(void* const* d_in, const int* in_sizes, int n_in,
                              void* d_out, int out_size) {
    const float* R     = (const float*)d_in[0];
    const float* t     = (const float*)d_in[1];
    const float* F0    = (const float*)d_in[2];
    const float* F1    = (const float*)d_in[3];
    const float* invD0 = (const float*)d_in[4];
    const float* invD1 = (const float*)d_in[5];
    const float* K     = (const float*)d_in[6];
    float* out = (float*)d_out;

    init_state_kernel<<<1, 96>>>(R, t);

    const int n = BB*CHW;
    sobel_kernel<<<(n + 255)/256, 256>>>(F1);

    for (int it = 0; it < 3; ++it) {
        accum_kernel<<<dim3(NBLK, BB), 256>>>(F0, F1, invD0, invD1, K, out, it == 2 ? 1 : 0);
        solve_kernel<<<BB, 32>>>(out, it == 2 ? 1 : 0);
    }
}

// round 2
// speedup vs baseline: 1.7011x; 1.7011x over previous
#include <cuda_runtime.h>
#include <cuda_fp16.h>
#include <math.h>

#define BB 8
#define CC 32
#define HH 120
#define WW 160
#define HW (HH*WW)
#define CHW (CC*HW)
#define OUT_ROW (12 + CHW)
#define NBLK (HW/256)   /* 75 */
#define OCC_THRES 0.1f

// ---------------- static device state (no dynamic allocation) ----------------
__device__ __half2 g_jf[BB*CHW];          // packed (jfx, jfy), fp16
__device__ float   g_R[BB][9];
__device__ float   g_t[BB][3];
__device__ float   g_part[BB][NBLK][27];

// ---------------- init: copy R,t inputs into iteration state ----------------
__global__ void init_state_kernel(const float* __restrict__ Rin,
                                  const float* __restrict__ tin) {
    int i = threadIdx.x;
    if (i < 72) g_R[i/9][i%9] = Rin[i];
    if (i < 24) g_t[i/3][i%3] = tin[i];
}

// ---------------- Sobel gradient (edge-clamped cross-correlation) ------------
__global__ void sobel_kernel(const float* __restrict__ F1) {
    int i = blockIdx.x*blockDim.x + threadIdx.x;
    if (i >= BB*CHW) return;
    int x  = i % WW;
    int y  = (i / WW) % HH;
    int bc = i / HW;
    const float* F = F1 + (size_t)bc*HW;
    int xm = max(x-1,0), xp = min(x+1,WW-1);
    int ym = max(y-1,0), yp = min(y+1,HH-1);
    float f_mm = F[ym*WW+xm], f_m0 = F[ym*WW+x], f_mp = F[ym*WW+xp];
    float f_0m = F[y *WW+xm],                    f_0p = F[y *WW+xp];
    float f_pm = F[yp*WW+xm], f_p0 = F[yp*WW+x], f_pp = F[yp*WW+xp];
    float dx = (f_mp - f_mm) + 2.0f*(f_0p - f_0m) + (f_pp - f_pm);
    float dy = (f_pm - f_mm) + 2.0f*(f_p0 - f_m0) + (f_pp - f_mp);
    float inv_mag = rsqrtf(dx*dx + dy*dy + 1e-8f);
    g_jf[i] = __floats2half2_rn(dx*inv_mag, dy*inv_mag);
}

// ---------------- per-pixel accumulation kernel ------------------------------
__global__ void __launch_bounds__(256)
accum_kernel(const float* __restrict__ F0, const float* __restrict__ F1,
             const float* __restrict__ invD0, const float* __restrict__ invD1,
             const float* __restrict__ Kmat, float* __restrict__ out, int last)
{
    const int b   = blockIdx.y;
    const int pix = blockIdx.x*blockDim.x + threadIdx.x;   // 0..19199 exactly
    const int x   = pix % WW;
    const int y   = pix / WW;

    // pose + intrinsics (broadcast loads)
    const float R0=g_R[b][0], R1=g_R[b][1], R2=g_R[b][2];
    const float R3=g_R[b][3], R4=g_R[b][4], R5=g_R[b][5];
    const float R6=g_R[b][6], R7=g_R[b][7], R8=g_R[b][8];
    const float t0=g_t[b][0], t1=g_t[b][1], t2=g_t[b][2];
    const float fx=Kmat[b*4+0], fy=Kmat[b*4+1], cx=Kmat[b*4+2], cy=Kmat[b*4+3];

    const float px = ((float)x - cx) / fx;
    const float py = ((float)y - cy) / fy;
    const float id0 = invD0[(size_t)b*HW + pix];

    // warp inverse depth: warped = R*[px,py,1] + t*invD0
    const float X = R0*px + R1*py + R2 + t0*id0;
    const float Y = R3*px + R4*py + R5 + t1*id0;
    const float S = R6*px + R7*py + R8 + t2*id0;
    const float u = (X/S)*fx + cx;
    const float v = (Y/S)*fy + cy;
    const float inv_z = id0 / S;

    const bool inview = (u > 0.0f) && (u < (float)(WW-1)) &&
                        (v > 0.0f) && (v < (float)(HH-1));

    // clipped bilinear setup
    const float uc = fminf(fmaxf(u, 0.0f), (float)(WW-1));
    const float vc = fminf(fmaxf(v, 0.0f), (float)(HH-1));
    const float x0f = floorf(uc), y0f = floorf(vc);
    const float wx = uc - x0f,  wy = vc - y0f;
    const int x0 = (int)x0f, y0 = (int)y0f;
    const int x1 = min(x0+1, WW-1), y1 = min(y0+1, HH-1);
    const int i00 = y0*WW+x0, i01 = y0*WW+x1, i10 = y1*WW+x0, i11 = y1*WW+x1;
    const float w00 = (1.0f-wx)*(1.0f-wy), w01 = wx*(1.0f-wy);
    const float w10 = (1.0f-wx)*wy,        w11 = wx*wy;

    // occlusion (invD1 warp, single channel)
    const float* D1 = invD1 + (size_t)b*HW;
    const float invD1w = D1[i00]*w00 + D1[i01]*w01 + D1[i10]*w10 + D1[i11]*w11;
    const bool occ = !((inv_z > invD1w - OCC_THRES) && inview);

    // jacobian warp: warped = R*[px,py,invD0] + t
    const float xj = R0*px + R1*py + R2*id0 + t0;
    const float yj = R3*px + R4*py + R5*id0 + t1;
    const float iz = R6*px + R7*py + R8*id0 + t2;
    const float Jx[6] = { fx*(-xj*yj), fx*(1.0f+xj*xj), fx*(-yj),
                          fx*iz,       0.0f,            fx*(-iz*xj) };
    const float Jy[6] = { fy*(-1.0f-yj*yj), fy*(xj*yj), fy*xj,
                          0.0f,             fy*iz,      fy*(-iz*yj) };

    // channel loop -> 5 scalar sums
    float saa = 0.f, sab = 0.f, sbb = 0.f, sar = 0.f, sbr = 0.f;
    const float*   F1b = F1   + (size_t)b*CHW;
    const float*   F0b = F0   + (size_t)b*CHW;
    const __half2* JFb = g_jf + (size_t)b*CHW;

    #pragma unroll 4
    for (int c = 0; c < CC; ++c) {
        const int o = c*HW;
        const float f1w = F1b[o+i00]*w00 + F1b[o+i01]*w01 +
                          F1b[o+i10]*w10 + F1b[o+i11]*w11;
        const float2 g00 = __half22float2(JFb[o+i00]);
        const float2 g01 = __half22float2(JFb[o+i01]);
        const float2 g10 = __half22float2(JFb[o+i10]);
        const float2 g11 = __half22float2(JFb[o+i11]);
        const float ax = g00.x*w00 + g01.x*w01 + g10.x*w10 + g11.x*w11;
        const float ay = g00.y*w00 + g01.y*w01 + g10.y*w10 + g11.y*w11;
        const float r   = occ ? 0.001f : (f1w - F0b[o + pix]);
        const float wgt = __fdividef(1.0f, 1.0f + r*r);
        const float wr  = wgt * r;
        saa += ax*ax;  sab += ax*ay;  sbb += ay*ay;
        sar += ax*wr;  sbr += ay*wr;
        if (last) __stwt(&out[(size_t)b*OUT_ROW + 12 + o + pix], wgt);
    }

    // per-pixel contribution: 21 (upper-tri 6x6) + 6 (rhs)
    float acc[27];
    int idx = 0;
    #pragma unroll
    for (int k = 0; k < 6; ++k)
        #pragma unroll
        for (int l = k; l < 6; ++l)
            acc[idx++] = saa*Jx[k]*Jx[l] + sab*(Jx[k]*Jy[l] + Jy[k]*Jx[l])
                       + sbb*Jy[k]*Jy[l];
    #pragma unroll
    for (int k = 0; k < 6; ++k)
        acc[idx++] = -(sar*Jx[k] + sbr*Jy[k]);

    // deterministic block reduction: warp shuffle -> smem -> single partial
    #pragma unroll
    for (int j = 0; j < 27; ++j) {
        float s = acc[j];
        #pragma unroll
        for (int off = 16; off > 0; off >>= 1)
            s += __shfl_down_sync(0xffffffffu, s, off);
        acc[j] = s;
    }
    __shared__ float sm[8][27];
    const int warp = threadIdx.x >> 5, lane = threadIdx.x & 31;
    if (lane == 0) {
        #pragma unroll
        for (int j = 0; j < 27; ++j) sm[warp][j] = acc[j];
    }
    __syncthreads();
    if (threadIdx.x < 27) {
        float s = 0.f;
        #pragma unroll
        for (int wp = 0; wp < 8; ++wp) s += sm[wp][threadIdx.x];
        g_part[b][blockIdx.x][threadIdx.x] = s;
    }
}

// ---------------- 6x6 Cholesky solve + se3 exp + pose update -----------------
__global__ void solve_kernel(float* __restrict__ out, int last) {
    const int b = blockIdx.x;
    __shared__ double acc[27];

    // pipelined fp64 reduction over 75 block partials (5 accumulators, fixed order)
    if (threadIdx.x < 27) {
        double s0 = 0.0, s1 = 0.0, s2 = 0.0, s3 = 0.0, s4 = 0.0;
        #pragma unroll
        for (int i = 0; i < 15; ++i) {
            s0 += (double)g_part[b][i     ][threadIdx.x];
            s1 += (double)g_part[b][i + 15][threadIdx.x];
            s2 += (double)g_part[b][i + 30][threadIdx.x];
            s3 += (double)g_part[b][i + 45][threadIdx.x];
            s4 += (double)g_part[b][i + 60][threadIdx.x];
        }
        acc[threadIdx.x] = ((s0 + s1) + (s2 + s3)) + s4;
    }
    __syncthreads();
    if (threadIdx.x != 0) return;

    // assemble SPD A (+damping) and rhs
    double A[6][6], rhs[6];
    {
        int idx = 0;
        for (int k = 0; k < 6; ++k)
            for (int l = k; l < 6; ++l) { A[k][l] = acc[idx]; A[l][k] = acc[idx]; ++idx; }
        for (int k = 0; k < 6; ++k) A[k][k] += 1e-4;
        for (int i = 0; i < 6; ++i) rhs[i] = acc[21+i];
    }

    // Cholesky A = L L^T (no pivoting needed: SPD)
    double L[6][6];
    #pragma unroll
    for (int j = 0; j < 6; ++j) {
        double d = A[j][j];
        #pragma unroll
        for (int k = 0; k < 6; ++k) if (k < j) d -= L[j][k]*L[j][k];
        const double ljj = sqrt(d);
        const double inv_ljj = 1.0 / ljj;
        L[j][j] = ljj;
        #pragma unroll
        for (int i = 0; i < 6; ++i) if (i > j) {
            double s = A[i][j];
            #pragma unroll
            for (int k = 0; k < 6; ++k) if (k < j) s -= L[i][k]*L[j][k];
            L[i][j] = s * inv_ljj;
        }
    }
    // forward/back substitution
    double yv[6], dp[6];
    #pragma unroll
    for (int i = 0; i < 6; ++i) {
        double s = rhs[i];
        #pragma unroll
        for (int k = 0; k < 6; ++k) if (k < i) s -= L[i][k]*yv[k];
        yv[i] = s / L[i][i];
    }
    #pragma unroll
    for (int i = 5; i >= 0; --i) {
        double s = yv[i];
        #pragma unroll
        for (int k = 0; k < 6; ++k) if (k > i) s -= L[k][i]*dp[k];
        dp[i] = s / L[i][i];
    }

    // se3 exponential
    const double w0 = dp[0], w1 = dp[1], w2 = dp[2];
    const double v0 = dp[3], v1 = dp[4], v2 = dp[5];
    const double th2  = w0*w0 + w1*w1 + w2*w2;
    const double th2e = th2 + 1e-12;
    const double th   = sqrt(th2e);
    double sth, cth;
    sincos(th, &sth, &cth);
    const double a   = sth / th;
    const double bbv = (1.0 - cth) / th2e;
    const double ccv = (1.0 - a) / th2e;
    const double Wm[3][3] = { {0.0, -w2,  w1},
                              {w2,  0.0, -w0},
                              {-w1, w0,  0.0} };
    double W2[3][3];
    #pragma unroll
    for (int i = 0; i < 3; ++i)
        #pragma unroll
        for (int j = 0; j < 3; ++j)
            W2[i][j] = Wm[i][0]*Wm[0][j] + Wm[i][1]*Wm[1][j] + Wm[i][2]*Wm[2][j];
    double dR[3][3], Vm[3][3];
    #pragma unroll
    for (int i = 0; i < 3; ++i)
        #pragma unroll
        for (int j = 0; j < 3; ++j) {
            const double I = (i == j) ? 1.0 : 0.0;
            dR[i][j] = I + a  * Wm[i][j] + bbv * W2[i][j];
            Vm[i][j] = I + bbv* Wm[i][j] + ccv * W2[i][j];
        }
    const double dt0 = Vm[0][0]*v0 + Vm[0][1]*v1 + Vm[0][2]*v2;
    const double dt1 = Vm[1][0]*v0 + Vm[1][1]*v1 + Vm[1][2]*v2;
    const double dt2 = Vm[2][0]*v0 + Vm[2][1]*v1 + Vm[2][2]*v2;

    // pose update: t = dR*t + dt ; R = dR*R
    double Rold[9], told[3];
    #pragma unroll
    for (int i = 0; i < 9; ++i) Rold[i] = (double)g_R[b][i];
    #pragma unroll
    for (int i = 0; i < 3; ++i) told[i] = (double)g_t[b][i];

    double tnew[3], Rnew[9];
    #pragma unroll
    for (int i = 0; i < 3; ++i) {
        tnew[i] = dR[i][0]*told[0] + dR[i][1]*told[1] + dR[i][2]*told[2]
                + ((i==0)?dt0:(i==1)?dt1:dt2);
        #pragma unroll
        for (int j = 0; j < 3; ++j)
            Rnew[i*3+j] = dR[i][0]*Rold[0*3+j] + dR[i][1]*Rold[1*3+j] + dR[i][2]*Rold[2*3+j];
    }
    #pragma unroll
    for (int i = 0; i < 9; ++i) g_R[b][i] = (float)Rnew[i];
    #pragma unroll
    for (int i = 0; i < 3; ++i) g_t[b][i] = (float)tnew[i];

    if (last) {
        #pragma unroll
        for (int i = 0; i < 9; ++i) out[(size_t)b*OUT_ROW + i]     = (float)Rnew[i];
        #pragma unroll
        for (int i = 0; i < 3; ++i) out[(size_t)b*OUT_ROW + 9 + i] = (float)tnew[i];
    }
}

// ---------------- launch ------------------------------------------------------
extern "C" void kernel_launch(void* const* d_in, const int* in_sizes, int n_in,
                              void* d_out, int out_size) {
    const float* R     = (const float*)d_in[0];
    const float* t     = (const float*)d_in[1];
    const float* F0    = (const float*)d_in[2];
    const float* F1    = (const float*)d_in[3];
    const float* invD0 = (const float*)d_in[4];
    const float* invD1 = (const float*)d_in[5];
    const float* K     = (const float*)d_in[6];
    float* out = (float*)d_out;

    init_state_kernel<<<1, 96>>>(R, t);

    const int n = BB*CHW;
    sobel_kernel<<<(n + 255)/256, 256>>>(F1);

    for (int it = 0; it < 3; ++it) {
        accum_kernel<<<dim3(NBLK, BB), 256>>>(F0, F1, invD0, invD1, K, out, it == 2 ? 1 : 0);
        solve_kernel<<<BB, 32>>>(out, it == 2 ? 1 : 0);
    }
}

// round 3
// speedup vs baseline: 2.4069x; 1.4149x over previous
#include <cuda_runtime.h>
#include <cuda_fp16.h>
#include <math.h>

#define BB 8
#define CC 32
#define HH 120
#define WW 160
#define HW (HH*WW)
#define CHW (CC*HW)
#define OUT_ROW (12 + CHW)
#define NBLK (HW/256)   /* 75 */
#define OCC_THRES 0.1f

// interleaved tap: F1 value + packed normalized gradients -> one LDG.64 per tap
struct __align__(8) Tap { float f1; __half2 jf; };

// ---------------- static device state (no dynamic allocation) ----------------
__device__ Tap   g_tap[BB*CHW];
__device__ float g_R[BB][9];
__device__ float g_t[BB][3];
__device__ float g_part[BB][NBLK][27];

// ---------------- init: copy R,t inputs into iteration state ----------------
__global__ void init_state_kernel(const float* __restrict__ Rin,
                                  const float* __restrict__ tin) {
    int i = threadIdx.x;
    if (i < 72) g_R[i/9][i%9] = Rin[i];
    if (i < 24) g_t[i/3][i%3] = tin[i];
}

// ------- Sobel gradient (edge-clamped cross-correlation) + F1 interleave -----
__global__ void sobel_kernel(const float* __restrict__ F1) {
    int i = blockIdx.x*blockDim.x + threadIdx.x;
    if (i >= BB*CHW) return;
    int x  = i % WW;
    int y  = (i / WW) % HH;
    int bc = i / HW;
    const float* F = F1 + (size_t)bc*HW;
    int xm = max(x-1,0), xp = min(x+1,WW-1);
    int ym = max(y-1,0), yp = min(y+1,HH-1);
    float f_mm = F[ym*WW+xm], f_m0 = F[ym*WW+x], f_mp = F[ym*WW+xp];
    float f_0m = F[y *WW+xm], f_00 = F[y*WW+x],  f_0p = F[y *WW+xp];
    float f_pm = F[yp*WW+xm], f_p0 = F[yp*WW+x], f_pp = F[yp*WW+xp];
    float dx = (f_mp - f_mm) + 2.0f*(f_0p - f_0m) + (f_pp - f_pm);
    float dy = (f_pm - f_mm) + 2.0f*(f_p0 - f_m0) + (f_pp - f_mp);
    float inv_mag = rsqrtf(dx*dx + dy*dy + 1e-8f);
    Tap tp;
    tp.f1 = f_00;
    tp.jf = __floats2half2_rn(dx*inv_mag, dy*inv_mag);
    g_tap[i] = tp;
}

// ---------------- per-pixel accumulation kernel ------------------------------
__global__ void __launch_bounds__(256)
accum_kernel(const float* __restrict__ F0, const float* __restrict__ invD0,
             const float* __restrict__ invD1, const float* __restrict__ Kmat,
             float* __restrict__ out, int last)
{
    const int b   = blockIdx.y;
    const int pix = blockIdx.x*blockDim.x + threadIdx.x;   // 0..19199 exactly
    const int x   = pix % WW;
    const int y   = pix / WW;

    // pose + intrinsics (broadcast loads)
    const float R0=g_R[b][0], R1=g_R[b][1], R2=g_R[b][2];
    const float R3=g_R[b][3], R4=g_R[b][4], R5=g_R[b][5];
    const float R6=g_R[b][6], R7=g_R[b][7], R8=g_R[b][8];
    const float t0=g_t[b][0], t1=g_t[b][1], t2=g_t[b][2];
    const float fx=Kmat[b*4+0], fy=Kmat[b*4+1], cx=Kmat[b*4+2], cy=Kmat[b*4+3];

    const float px = ((float)x - cx) / fx;
    const float py = ((float)y - cy) / fy;
    const float id0 = invD0[(size_t)b*HW + pix];

    // warp inverse depth: warped = R*[px,py,1] + t*invD0
    const float X = R0*px + R1*py + R2 + t0*id0;
    const float Y = R3*px + R4*py + R5 + t1*id0;
    const float S = R6*px + R7*py + R8 + t2*id0;
    const float u = (X/S)*fx + cx;
    const float v = (Y/S)*fy + cy;
    const float inv_z = id0 / S;

    const bool inview = (u > 0.0f) && (u < (float)(WW-1)) &&
                        (v > 0.0f) && (v < (float)(HH-1));

    // clipped bilinear setup
    const float uc = fminf(fmaxf(u, 0.0f), (float)(WW-1));
    const float vc = fminf(fmaxf(v, 0.0f), (float)(HH-1));
    const float x0f = floorf(uc), y0f = floorf(vc);
    const float wx = uc - x0f,  wy = vc - y0f;
    const int x0 = (int)x0f, y0 = (int)y0f;
    const int x1 = min(x0+1, WW-1), y1 = min(y0+1, HH-1);
    const int i00 = y0*WW+x0, i01 = y0*WW+x1, i10 = y1*WW+x0, i11 = y1*WW+x1;
    const float w00 = (1.0f-wx)*(1.0f-wy), w01 = wx*(1.0f-wy);
    const float w10 = (1.0f-wx)*wy,        w11 = wx*wy;

    // occlusion (invD1 warp, single channel)
    const float* D1 = invD1 + (size_t)b*HW;
    const float invD1w = D1[i00]*w00 + D1[i01]*w01 + D1[i10]*w10 + D1[i11]*w11;
    const bool occ = !((inv_z > invD1w - OCC_THRES) && inview);

    // jacobian warp: warped = R*[px,py,invD0] + t
    const float xj = R0*px + R1*py + R2*id0 + t0;
    const float yj = R3*px + R4*py + R5*id0 + t1;
    const float iz = R6*px + R7*py + R8*id0 + t2;
    const float Jx[6] = { fx*(-xj*yj), fx*(1.0f+xj*xj), fx*(-yj),
                          fx*iz,       0.0f,            fx*(-iz*xj) };
    const float Jy[6] = { fy*(-1.0f-yj*yj), fy*(xj*yj), fy*xj,
                          0.0f,             fy*iz,      fy*(-iz*yj) };

    // channel loop -> 5 scalar sums
    float saa = 0.f, sab = 0.f, sbb = 0.f, sar = 0.f, sbr = 0.f;
    const float* F0b = F0    + (size_t)b*CHW;
    const Tap*   Tb  = g_tap + (size_t)b*CHW;

    #pragma unroll 4
    for (int c = 0; c < CC; ++c) {
        const int o = c*HW;
        const Tap tp00 = Tb[o+i00];
        const Tap tp01 = Tb[o+i01];
        const Tap tp10 = Tb[o+i10];
        const Tap tp11 = Tb[o+i11];
        const float f1w = tp00.f1*w00 + tp01.f1*w01 + tp10.f1*w10 + tp11.f1*w11;
        const float2 g00 = __half22float2(tp00.jf);
        const float2 g01 = __half22float2(tp01.jf);
        const float2 g10 = __half22float2(tp10.jf);
        const float2 g11 = __half22float2(tp11.jf);
        const float ax = g00.x*w00 + g01.x*w01 + g10.x*w10 + g11.x*w11;
        const float ay = g00.y*w00 + g01.y*w01 + g10.y*w10 + g11.y*w11;
        const float r   = occ ? 0.001f : (f1w - F0b[o + pix]);
        const float wgt = __fdividef(1.0f, 1.0f + r*r);
        const float wr  = wgt * r;
        saa += ax*ax;  sab += ax*ay;  sbb += ay*ay;
        sar += ax*wr;  sbr += ay*wr;
        if (last) __stwt(&out[(size_t)b*OUT_ROW + 12 + o + pix], wgt);
    }

    // per-pixel contribution: 21 (upper-tri 6x6) + 6 (rhs)
    float acc[27];
    int idx = 0;
    #pragma unroll
    for (int k = 0; k < 6; ++k)
        #pragma unroll
        for (int l = k; l < 6; ++l)
            acc[idx++] = saa*Jx[k]*Jx[l] + sab*(Jx[k]*Jy[l] + Jy[k]*Jx[l])
                       + sbb*Jy[k]*Jy[l];
    #pragma unroll
    for (int k = 0; k < 6; ++k)
        acc[idx++] = -(sar*Jx[k] + sbr*Jy[k]);

    // deterministic block reduction: warp shuffle -> smem -> single partial
    #pragma unroll
    for (int j = 0; j < 27; ++j) {
        float s = acc[j];
        #pragma unroll
        for (int off = 16; off > 0; off >>= 1)
            s += __shfl_down_sync(0xffffffffu, s, off);
        acc[j] = s;
    }
    __shared__ float sm[8][27];
    const int warp = threadIdx.x >> 5, lane = threadIdx.x & 31;
    if (lane == 0) {
        #pragma unroll
        for (int j = 0; j < 27; ++j) sm[warp][j] = acc[j];
    }
    __syncthreads();
    if (threadIdx.x < 27) {
        float s = 0.f;
        #pragma unroll
        for (int wp = 0; wp < 8; ++wp) s += sm[wp][threadIdx.x];
        g_part[b][blockIdx.x][threadIdx.x] = s;
    }
}

// ------- 6x6 Cholesky solve (fp32) + se3 exp (fp32) + pose update ------------
__global__ void solve_kernel(float* __restrict__ out, int last) {
    const int b = blockIdx.x;
    __shared__ float acc[27];

    // pipelined fp64 cross-block reduction (fixed order), result to fp32
    if (threadIdx.x < 27) {
        double s0 = 0.0, s1 = 0.0, s2 = 0.0, s3 = 0.0, s4 = 0.0;
        #pragma unroll
        for (int i = 0; i < 15; ++i) {
            s0 += (double)g_part[b][i     ][threadIdx.x];
            s1 += (double)g_part[b][i + 15][threadIdx.x];
            s2 += (double)g_part[b][i + 30][threadIdx.x];
            s3 += (double)g_part[b][i + 45][threadIdx.x];
            s4 += (double)g_part[b][i + 60][threadIdx.x];
        }
        acc[threadIdx.x] = (float)(((s0 + s1) + (s2 + s3)) + s4);
    }
    __syncthreads();
    if (threadIdx.x != 0) return;

    // assemble SPD A (+damping) and rhs  (all fp32 from here on)
    float A[6][6], rhs[6];
    {
        int idx = 0;
        #pragma unroll
        for (int k = 0; k < 6; ++k)
            #pragma unroll
            for (int l = 0; l < 6; ++l) if (l >= k) { A[k][l] = acc[idx]; A[l][k] = acc[idx]; ++idx; }
        #pragma unroll
        for (int k = 0; k < 6; ++k) A[k][k] += 1e-4f;
        #pragma unroll
        for (int i = 0; i < 6; ++i) rhs[i] = acc[21+i];
    }

    // Cholesky A = L L^T (SPD, no pivoting)
    float L[6][6];
    #pragma unroll
    for (int j = 0; j < 6; ++j) {
        float d = A[j][j];
        #pragma unroll
        for (int k = 0; k < 6; ++k) if (k < j) d -= L[j][k]*L[j][k];
        const float ljj = sqrtf(d);
        const float inv_ljj = 1.0f / ljj;
        L[j][j] = ljj;
        #pragma unroll
        for (int i = 0; i < 6; ++i) if (i > j) {
            float s = A[i][j];
            #pragma unroll
            for (int k = 0; k < 6; ++k) if (k < j) s -= L[i][k]*L[j][k];
            L[i][j] = s * inv_ljj;
        }
    }
    // forward/back substitution
    float yv[6], dp[6];
    #pragma unroll
    for (int i = 0; i < 6; ++i) {
        float s = rhs[i];
        #pragma unroll
        for (int k = 0; k < 6; ++k) if (k < i) s -= L[i][k]*yv[k];
        yv[i] = s / L[i][i];
    }
    #pragma unroll
    for (int i = 5; i >= 0; --i) {
        float s = yv[i];
        #pragma unroll
        for (int k = 0; k < 6; ++k) if (k > i) s -= L[k][i]*dp[k];
        dp[i] = s / L[i][i];
    }

    // se3 exponential (fp32)
    const float w0 = dp[0], w1 = dp[1], w2 = dp[2];
    const float v0 = dp[3], v1 = dp[4], v2 = dp[5];
    const float th2  = w0*w0 + w1*w1 + w2*w2;
    const float th2e = th2 + 1e-12f;
    const float th   = sqrtf(th2e);
    float sth, cth;
    sincosf(th, &sth, &cth);
    const float a   = sth / th;
    const float bbv = (1.0f - cth) / th2e;
    const float ccv = (1.0f - a) / th2e;
    const float Wm[3][3] = { {0.0f, -w2,  w1},
                             {w2,  0.0f, -w0},
                             {-w1, w0,  0.0f} };
    float W2[3][3];
    #pragma unroll
    for (int i = 0; i < 3; ++i)
        #pragma unroll
        for (int j = 0; j < 3; ++j)
            W2[i][j] = Wm[i][0]*Wm[0][j] + Wm[i][1]*Wm[1][j] + Wm[i][2]*Wm[2][j];
    float dR[3][3], Vm[3][3];
    #pragma unroll
    for (int i = 0; i < 3; ++i)
        #pragma unroll
        for (int j = 0; j < 3; ++j) {
            const float I = (i == j) ? 1.0f : 0.0f;
            dR[i][j] = I + a  * Wm[i][j] + bbv * W2[i][j];
            Vm[i][j] = I + bbv* Wm[i][j] + ccv * W2[i][j];
        }
    const float dt0 = Vm[0][0]*v0 + Vm[0][1]*v1 + Vm[0][2]*v2;
    const float dt1 = Vm[1][0]*v0 + Vm[1][1]*v1 + Vm[1][2]*v2;
    const float dt2 = Vm[2][0]*v0 + Vm[2][1]*v1 + Vm[2][2]*v2;

    // pose update: t = dR*t + dt ; R = dR*R
    float Rold[9], told[3];
    #pragma unroll
    for (int i = 0; i < 9; ++i) Rold[i] = g_R[b][i];
    #pragma unroll
    for (int i = 0; i < 3; ++i) told[i] = g_t[b][i];

    float tnew[3], Rnew[9];
    #pragma unroll
    for (int i = 0; i < 3; ++i) {
        tnew[i] = dR[i][0]*told[0] + dR[i][1]*told[1] + dR[i][2]*told[2]
                + ((i==0)?dt0:(i==1)?dt1:dt2);
        #pragma unroll
        for (int j = 0; j < 3; ++j)
            Rnew[i*3+j] = dR[i][0]*Rold[0*3+j] + dR[i][1]*Rold[1*3+j] + dR[i][2]*Rold[2*3+j];
    }
    #pragma unroll
    for (int i = 0; i < 9; ++i) g_R[b][i] = Rnew[i];
    #pragma unroll
    for (int i = 0; i < 3; ++i) g_t[b][i] = Rnew ? tnew[i] : tnew[i];

    if (last) {
        #pragma unroll
        for (int i = 0; i < 9; ++i) out[(size_t)b*OUT_ROW + i]     = Rnew[i];
        #pragma unroll
        for (int i = 0; i < 3; ++i) out[(size_t)b*OUT_ROW + 9 + i] = tnew[i];
    }
}

// ---------------- launch ------------------------------------------------------
extern "C" void kernel_launch(void* const* d_in, const int* in_sizes, int n_in,
                              void* d_out, int out_size) {
    const float* R     = (const float*)d_in[0];
    const float* t     = (const float*)d_in[1];
    const float* F0    = (const float*)d_in[2];
    const float* F1    = (const float*)d_in[3];
    const float* invD0 = (const float*)d_in[4];
    const float* invD1 = (const float*)d_in[5];
    const float* K     = (const float*)d_in[6];
    float* out = (float*)d_out;

    init_state_kernel<<<1, 96>>>(R, t);

    const int n = BB*CHW;
    sobel_kernel<<<(n + 255)/256, 256>>>(F1);

    for (int it = 0; it < 3; ++it) {
        accum_kernel<<<dim3(NBLK, BB), 256>>>(F0, invD0, invD1, K, out, it == 2 ? 1 : 0);
        solve_kernel<<<BB, 32>>>(out, it == 2 ? 1 : 0);
    }
}

// round 5
// speedup vs baseline: 2.5101x; 1.0429x over previous
#include <cuda_runtime.h>
#include <cuda_fp16.h>
#include <math.h>

#define BB 8
#define CC 32
#define HH 120
#define WW 160
#define HW (HH*WW)
#define CHW (CC*HW)
#define OUT_ROW (12 + CHW)
#define NBLK (HW/256)   /* 75 */
#define OCC_THRES 0.1f

// interleaved tap: F1 value + packed normalized gradients -> one LDG.64 per tap
struct __align__(8) Tap { float f1; __half2 jf; };

// ---------------- static device state (no dynamic allocation) ----------------
__device__ Tap   g_tap[BB*CHW];
__device__ float g_R[BB][9];
__device__ float g_t[BB][3];
__device__ float g_part[BB][NBLK][27];
__device__ int   g_cnt[3][BB];   // zero-init; self-resetting per replay

// ------- Sobel (vectorized, 4 px/thread) + F1 interleave + pose init ---------
__global__ void sobel_kernel(const float* __restrict__ F1,
                             const float* __restrict__ Rin,
                             const float* __restrict__ tin) {
    // fold pose init into first block
    if (blockIdx.x == 0) {
        int i = threadIdx.x;
        if (i < 72) g_R[i/9][i%9] = Rin[i];
        if (i < 24) g_t[i/3][i%3] = tin[i];
    }
    const int g = blockIdx.x*blockDim.x + threadIdx.x;     // one per 4 pixels
    if (g >= BB*CHW/4) return;
    const int i4 = g * 4;
    const int x  = i4 % WW;                                 // multiple of 4
    const int y  = (i4 / WW) % HH;
    const int bc = i4 / HW;
    const float* F = F1 + (size_t)bc*HW;

    const int ym = max(y-1,0)*WW, y0 = y*WW, yp = min(y+1,HH-1)*WW;
    const int xl = max(x-1,0), xr = min(x+4, WW-1);

    // per row: aligned float4 over [x..x+3] plus left/right halo scalars
    float rm[6], r0[6], rp[6];
    {
        float4 a = *(const float4*)(F + ym + x);
        rm[0]=F[ym+xl]; rm[1]=a.x; rm[2]=a.y; rm[3]=a.z; rm[4]=a.w; rm[5]=F[ym+xr];
        float4 b = *(const float4*)(F + y0 + x);
        r0[0]=F[y0+xl]; r0[1]=b.x; r0[2]=b.y; r0[3]=b.z; r0[4]=b.w; r0[5]=F[y0+xr];
        float4 c = *(const float4*)(F + yp + x);
        rp[0]=F[yp+xl]; rp[1]=c.x; rp[2]=c.y; rp[3]=c.z; rp[4]=c.w; rp[5]=F[yp+xr];
    }

    Tap tp[4];
    #pragma unroll
    for (int k = 0; k < 4; ++k) {
        const float f_mm=rm[k], f_m0=rm[k+1], f_mp=rm[k+2];
        const float f_0m=r0[k], f_00=r0[k+1], f_0p=r0[k+2];
        const float f_pm=rp[k], f_p0=rp[k+1], f_pp=rp[k+2];
        const float dx = (f_mp - f_mm) + 2.0f*(f_0p - f_0m) + (f_pp - f_pm);
        const float dy = (f_pm - f_mm) + 2.0f*(f_p0 - f_m0) + (f_pp - f_mp);
        const float inv_mag = rsqrtf(dx*dx + dy*dy + 1e-8f);
        tp[k].f1 = f_00;
        tp[k].jf = __floats2half2_rn(dx*inv_mag, dy*inv_mag);
    }
    // two 16B stores (i4 is 4-Tap aligned -> 32B aligned)
    *(float4*)(&g_tap[i4])   = *(float4*)(&tp[0]);
    *(float4*)(&g_tap[i4+2]) = *(float4*)(&tp[2]);
}

// ----- fused per-pixel accumulation + last-block reduction/solve -------------
__global__ void __launch_bounds__(256)
accum_kernel(const float* __restrict__ F0, const float* __restrict__ invD0,
             const float* __restrict__ invD1, const float* __restrict__ Kmat,
             float* __restrict__ out, int it)
{
    const int  b    = blockIdx.y;
    const int  last = (it == 2);
    const int  pix  = blockIdx.x*blockDim.x + threadIdx.x;   // 0..19199 exactly
    const int  x    = pix % WW;
    const int  y    = pix / WW;

    // pose + intrinsics (broadcast loads)
    const float R0=g_R[b][0], R1=g_R[b][1], R2=g_R[b][2];
    const float R3=g_R[b][3], R4=g_R[b][4], R5=g_R[b][5];
    const float R6=g_R[b][6], R7=g_R[b][7], R8=g_R[b][8];
    const float t0=g_t[b][0], t1=g_t[b][1], t2=g_t[b][2];
    const float fx=Kmat[b*4+0], fy=Kmat[b*4+1], cx=Kmat[b*4+2], cy=Kmat[b*4+3];

    const float px = ((float)x - cx) / fx;
    const float py = ((float)y - cy) / fy;
    const float id0 = invD0[(size_t)b*HW + pix];

    // warp inverse depth: warped = R*[px,py,1] + t*invD0
    const float X = R0*px + R1*py + R2 + t0*id0;
    const float Y = R3*px + R4*py + R5 + t1*id0;
    const float S = R6*px + R7*py + R8 + t2*id0;
    const float u = (X/S)*fx + cx;
    const float v = (Y/S)*fy + cy;
    const float inv_z = id0 / S;

    const bool inview = (u > 0.0f) && (u < (float)(WW-1)) &&
                        (v > 0.0f) && (v < (float)(HH-1));

    // clipped bilinear setup
    const float uc = fminf(fmaxf(u, 0.0f), (float)(WW-1));
    const float vc = fminf(fmaxf(v, 0.0f), (float)(HH-1));
    const float x0f = floorf(uc), y0f = floorf(vc);
    const float wx = uc - x0f,  wy = vc - y0f;
    const int x0 = (int)x0f, y0 = (int)y0f;
    const int x1 = min(x0+1, WW-1), y1 = min(y0+1, HH-1);
    const int i00 = y0*WW+x0, i01 = y0*WW+x1, i10 = y1*WW+x0, i11 = y1*WW+x1;
    const float w00 = (1.0f-wx)*(1.0f-wy), w01 = wx*(1.0f-wy);
    const float w10 = (1.0f-wx)*wy,        w11 = wx*wy;

    // occlusion (invD1 warp, single channel)
    const float* D1 = invD1 + (size_t)b*HW;
    const float invD1w = D1[i00]*w00 + D1[i01]*w01 + D1[i10]*w10 + D1[i11]*w11;
    const bool occ = !((inv_z > invD1w - OCC_THRES) && inview);

    // jacobian warp: warped = R*[px,py,invD0] + t
    const float xj = R0*px + R1*py + R2*id0 + t0;
    const float yj = R3*px + R4*py + R5*id0 + t1;
    const float iz = R6*px + R7*py + R8*id0 + t2;
    const float Jx[6] = { fx*(-xj*yj), fx*(1.0f+xj*xj), fx*(-yj),
                          fx*iz,       0.0f,            fx*(-iz*xj) };
    const float Jy[6] = { fy*(-1.0f-yj*yj), fy*(xj*yj), fy*xj,
                          0.0f,             fy*iz,      fy*(-iz*yj) };

    // channel loop -> 5 scalar sums
    float saa = 0.f, sab = 0.f, sbb = 0.f, sar = 0.f, sbr = 0.f;
    const float* F0b = F0    + (size_t)b*CHW;
    const Tap*   Tb  = g_tap + (size_t)b*CHW;

    #pragma unroll 4
    for (int c = 0; c < CC; ++c) {
        const int o = c*HW;
        const Tap tp00 = Tb[o+i00];
        const Tap tp01 = Tb[o+i01];
        const Tap tp10 = Tb[o+i10];
        const Tap tp11 = Tb[o+i11];
        const float f1w = tp00.f1*w00 + tp01.f1*w01 + tp10.f1*w10 + tp11.f1*w11;
        const float2 g00 = __half22float2(tp00.jf);
        const float2 g01 = __half22float2(tp01.jf);
        const float2 g10 = __half22float2(tp10.jf);
        const float2 g11 = __half22float2(tp11.jf);
        const float ax = g00.x*w00 + g01.x*w01 + g10.x*w10 + g11.x*w11;
        const float ay = g00.y*w00 + g01.y*w01 + g10.y*w10 + g11.y*w11;
        const float r   = occ ? 0.001f : (f1w - F0b[o + pix]);
        const float wgt = __fdividef(1.0f, 1.0f + r*r);
        const float wr  = wgt * r;
        saa += ax*ax;  sab += ax*ay;  sbb += ay*ay;
        sar += ax*wr;  sbr += ay*wr;
        if (last) __stwt(&out[(size_t)b*OUT_ROW + 12 + o + pix], wgt);
    }

    // per-pixel contribution: 21 (upper-tri 6x6) + 6 (rhs)
    float acc[27];
    {
        int idx = 0;
        #pragma unroll
        for (int k = 0; k < 6; ++k)
            #pragma unroll
            for (int l = k; l < 6; ++l)
                acc[idx++] = saa*Jx[k]*Jx[l] + sab*(Jx[k]*Jy[l] + Jy[k]*Jx[l])
                           + sbb*Jy[k]*Jy[l];
        #pragma unroll
        for (int k = 0; k < 6; ++k)
            acc[idx++] = -(sar*Jx[k] + sbr*Jy[k]);
    }

    // deterministic block reduction: warp shuffle -> smem -> single partial
    #pragma unroll
    for (int j = 0; j < 27; ++j) {
        float s = acc[j];
        #pragma unroll
        for (int off = 16; off > 0; off >>= 1)
            s += __shfl_down_sync(0xffffffffu, s, off);
        acc[j] = s;
    }
    __shared__ float sm[8][27];
    const int warp = threadIdx.x >> 5, lane = threadIdx.x & 31;
    if (lane == 0) {
        #pragma unroll
        for (int j = 0; j < 27; ++j) sm[warp][j] = acc[j];
    }
    __syncthreads();
    if (threadIdx.x < 27) {
        float s = 0.f;
        #pragma unroll
        for (int wp = 0; wp < 8; ++wp) s += sm[wp][threadIdx.x];
        g_part[b][blockIdx.x][threadIdx.x] = s;
    }

    // ---------- last-arriving block for this batch does reduce + solve -------
    __syncthreads();                       // g_part stores complete block-wide
    __shared__ int amLast;
    __threadfence();                       // publish g_part slice
    if (threadIdx.x == 0)
        amLast = (atomicAdd(&g_cnt[it][b], 1) == NBLK - 1);
    __syncthreads();
    if (!amLast) return;
    __threadfence();                       // acquire other blocks' g_part

    __shared__ float red[27];
    if (threadIdx.x < 27) {
        double s0 = 0.0, s1 = 0.0, s2 = 0.0, s3 = 0.0, s4 = 0.0;
        #pragma unroll
        for (int i = 0; i < 15; ++i) {
            s0 += (double)g_part[b][i     ][threadIdx.x];
            s1 += (double)g_part[b][i + 15][threadIdx.x];
            s2 += (double)g_part[b][i + 30][threadIdx.x];
            s3 += (double)g_part[b][i + 45][threadIdx.x];
            s4 += (double)g_part[b][i + 60][threadIdx.x];
        }
        red[threadIdx.x] = (float)(((s0 + s1) + (s2 + s3)) + s4);
    }
    __syncthreads();
    if (threadIdx.x != 0) return;

    g_cnt[it][b] = 0;                      // reset for next graph replay

    // assemble SPD A (+damping) and rhs  (fp32)
    float A[6][6], rhs[6];
    {
        int idx = 0;
        #pragma unroll
        for (int k = 0; k < 6; ++k)
            #pragma unroll
            for (int l = 0; l < 6; ++l) if (l >= k) { A[k][l] = red[idx]; A[l][k] = red[idx]; ++idx; }
        #pragma unroll
        for (int k = 0; k < 6; ++k) A[k][k] += 1e-4f;
        #pragma unroll
        for (int i = 0; i < 6; ++i) rhs[i] = red[21+i];
    }

    // Cholesky A = L L^T (SPD, no pivoting) — accurate fp32 ops
    float L[6][6];
    #pragma unroll
    for (int j = 0; j < 6; ++j) {
        float d = A[j][j];
        #pragma unroll
        for (int k = 0; k < 6; ++k) if (k < j) d -= L[j][k]*L[j][k];
        const float ljj = sqrtf(d);
        const float inv_ljj = 1.0f / ljj;
        L[j][j] = ljj;
        #pragma unroll
        for (int i = 0; i < 6; ++i) if (i > j) {
            float s = A[i][j];
            #pragma unroll
            for (int k = 0; k < 6; ++k) if (k < j) s -= L[i][k]*L[j][k];
            L[i][j] = s * inv_ljj;
        }
    }
    // forward/back substitution
    float yv[6], dp[6];
    #pragma unroll
    for (int i = 0; i < 6; ++i) {
        float s = rhs[i];
        #pragma unroll
        for (int k = 0; k < 6; ++k) if (k < i) s -= L[i][k]*yv[k];
        yv[i] = s / L[i][i];
    }
    #pragma unroll
    for (int i = 5; i >= 0; --i) {
        float s = yv[i];
        #pragma unroll
        for (int k = 0; k < 6; ++k) if (k > i) s -= L[k][i]*dp[k];
        dp[i] = s / L[i][i];
    }

    // se3 exponential (fp32, accurate sincosf/sqrtf)
    const float w0 = dp[0], w1 = dp[1], w2 = dp[2];
    const float v0 = dp[3], v1 = dp[4], v2 = dp[5];
    const float th2  = w0*w0 + w1*w1 + w2*w2;
    const float th2e = th2 + 1e-12f;
    const float th   = sqrtf(th2e);
    float sth, cth;
    sincosf(th, &sth, &cth);
    const float a   = sth / th;
    const float bbv = (1.0f - cth) / th2e;
    const float ccv = (1.0f - a) / th2e;
    const float Wm[3][3] = { {0.0f, -w2,  w1},
                             {w2,  0.0f, -w0},
                             {-w1, w0,  0.0f} };
    float W2[3][3];
    #pragma unroll
    for (int i = 0; i < 3; ++i)
        #pragma unroll
        for (int j = 0; j < 3; ++j)
            W2[i][j] = Wm[i][0]*Wm[0][j] + Wm[i][1]*Wm[1][j] + Wm[i][2]*Wm[2][j];
    float dR[3][3], Vm[3][3];
    #pragma unroll
    for (int i = 0; i < 3; ++i)
        #pragma unroll
        for (int j = 0; j < 3; ++j) {
            const float I = (i == j) ? 1.0f : 0.0f;
            dR[i][j] = I + a  * Wm[i][j] + bbv * W2[i][j];
            Vm[i][j] = I + bbv* Wm[i][j] + ccv * W2[i][j];
        }
    const float dt0 = Vm[0][0]*v0 + Vm[0][1]*v1 + Vm[0][2]*v2;
    const float dt1 = Vm[1][0]*v0 + Vm[1][1]*v1 + Vm[1][2]*v2;
    const float dt2 = Vm[2][0]*v0 + Vm[2][1]*v1 + Vm[2][2]*v2;

    // pose update: t = dR*t + dt ; R = dR*R
    float Rold[9], told[3];
    #pragma unroll
    for (int i = 0; i < 9; ++i) Rold[i] = g_R[b][i];
    #pragma unroll
    for (int i = 0; i < 3; ++i) told[i] = g_t[b][i];

    float tnew[3], Rnew[9];
    #pragma unroll
    for (int i = 0; i < 3; ++i) {
        tnew[i] = dR[i][0]*told[0] + dR[i][1]*told[1] + dR[i][2]*told[2]
                + ((i==0)?dt0:(i==1)?dt1:dt2);
        #pragma unroll
        for (int j = 0; j < 3; ++j)
            Rnew[i*3+j] = dR[i][0]*Rold[0*3+j] + dR[i][1]*Rold[1*3+j] + dR[i][2]*Rold[2*3+j];
    }
    #pragma unroll
    for (int i = 0; i < 9; ++i) g_R[b][i] = Rnew[i];
    #pragma unroll
    for (int i = 0; i < 3; ++i) g_t[b][i] = tnew[i];

    if (last) {
        #pragma unroll
        for (int i = 0; i < 9; ++i) out[(size_t)b*OUT_ROW + i]     = Rnew[i];
        #pragma unroll
        for (int i = 0; i < 3; ++i) out[(size_t)b*OUT_ROW + 9 + i] = tnew[i];
    }
}

// ---------------- launch ------------------------------------------------------
extern "C" void kernel_launch(void* const* d_in, const int* in_sizes, int n_in,
                              void* d_out, int out_size) {
    const float* R     = (const float*)d_in[0];
    const float* t     = (const float*)d_in[1];
    const float* F0    = (const float*)d_in[2];
    const float* F1    = (const float*)d_in[3];
    const float* invD0 = (const float*)d_in[4];
    const float* invD1 = (const float*)d_in[5];
    const float* K     = (const float*)d_in[6];
    float* out = (float*)d_out;

    const int n4 = BB*CHW/4;
    sobel_kernel<<<(n4 + 255)/256, 256>>>(F1, R, t);

    for (int it = 0; it < 3; ++it)
        accum_kernel<<<dim3(NBLK, BB), 256>>>(F0, invD0, invD1, K, out, it);
}